// round 13
// baseline (speedup 1.0000x reference)
#include <cuda_runtime.h>
#include <cuda_bf16.h>
#include <math.h>
#include <stdint.h>

#define NPIX 16384
#define CDIM 128
#define NB 2
#define NV 6
#define BVI 12
#define WW 128

typedef uint16_t u16;
typedef uint32_t u32;

// ---------------- scratch ----------------
__device__ float g_bufA[(size_t)BVI * CDIM * NPIX];     // merge1 out (fp32)
__device__ float g_bufB[(size_t)BVI * CDIM * NPIX];     // g2 (fp32)
__device__ float g_alp [(size_t)BVI * NPIX];
__device__ float g_u   [(size_t)NB * CDIM * NPIX];
// bf16 hi/lo planes
__device__ __align__(16) u16 g_dwh [(size_t)BVI * CDIM * NPIX], g_dwl [(size_t)BVI * CDIM * NPIX];
__device__ __align__(16) u16 g_m2h [(size_t)BVI * CDIM * NPIX], g_m2l [(size_t)BVI * CDIM * NPIX];
__device__ __align__(16) u16 g_g1h [(size_t)BVI * CDIM * NPIX], g_g1l [(size_t)BVI * CDIM * NPIX];
__device__ __align__(16) u16 g_plh [(size_t)NB * CDIM * NPIX],  g_pll [(size_t)NB * CDIM * NPIX];
// weight hi/lo planes (k-major; GRU weights hidden/gate row-interleaved)
__device__ __align__(16) u16 g_wm1h[128 * 256], g_wm1l[128 * 256];
__device__ __align__(16) u16 g_wm2h[128 * 128], g_wm2l[128 * 128];
__device__ __align__(16) u16 g_wgh [256 * 128], g_wgl [256 * 128];
__device__ __align__(16) u16 g_wgbh[256 * 128], g_wgbl[256 * 128];
__device__ __align__(16) u16 g_wuph[128 * 128], g_wupl[128 * 128];

__device__ __forceinline__ float gelu_exact(float x) {
    return 0.5f * x * (1.0f + erff(x * 0.70710678118654752f));
}
__device__ __forceinline__ u32 smem_u32(const void* p) {
    return (u32)__cvta_generic_to_shared(p);
}
__device__ __forceinline__ void split_pack(float v0, float v1, u32& hi, u32& lo) {
    asm("cvt.rn.bf16x2.f32 %0, %1, %2;" : "=r"(hi) : "f"(v1), "f"(v0));
    float r0 = v0 - __uint_as_float(hi << 16);
    float r1 = v1 - __uint_as_float(hi & 0xffff0000u);
    asm("cvt.rn.bf16x2.f32 %0, %1, %2;" : "=r"(lo) : "f"(r1), "f"(r0));
}
__device__ __forceinline__ void ldm_x4(u32* r, u32 addr) {
    asm volatile("ldmatrix.sync.aligned.m8n8.x4.shared.b16 {%0,%1,%2,%3}, [%4];"
                 : "=r"(r[0]), "=r"(r[1]), "=r"(r[2]), "=r"(r[3]) : "r"(addr));
}
__device__ __forceinline__ void ldm_x4t(u32* r, u32 addr) {
    asm volatile("ldmatrix.sync.aligned.m8n8.x4.trans.shared.b16 {%0,%1,%2,%3}, [%4];"
                 : "=r"(r[0]), "=r"(r[1]), "=r"(r[2]), "=r"(r[3]) : "r"(addr));
}
__device__ __forceinline__ void mma_bf16(float* d, const u32* a, const u32* b) {
    asm volatile(
        "mma.sync.aligned.m16n8k16.row.col.f32.bf16.bf16.f32 "
        "{%0,%1,%2,%3}, {%4,%5,%6,%7}, {%8,%9}, {%0,%1,%2,%3};"
        : "+f"(d[0]), "+f"(d[1]), "+f"(d[2]), "+f"(d[3])
        : "r"(a[0]), "r"(a[1]), "r"(a[2]), "r"(a[3]), "r"(b[0]), "r"(b[1]));
}
__device__ __forceinline__ void cpasync16(u32 dst, const void* src) {
    asm volatile("cp.async.cg.shared.global [%0], [%1], 16;" :: "r"(dst), "l"(src));
}
__device__ __forceinline__ void cp_commit() {
    asm volatile("cp.async.commit_group;" ::: "memory");
}

// ---------------- common tile constants ----------------
constexpr int KC = 32;
constexpr int A_PITCH_B = 80;
constexpr int A_PLANE_B = 128 * A_PITCH_B;       // 10240
constexpr int A_STAGE_B = 2 * A_PLANE_B;         // 20480 (hi+lo)
constexpr int BB_PITCH = 272;
constexpr int BB_PLANE = KC * BB_PITCH;          // 8704
constexpr int BB_STAGE = 2 * BB_PLANE;           // hi+lo 17408
constexpr int OFF_B0 = 2 * A_STAGE_B;            // 40960
constexpr int GSMEM  = OFF_B0 + 2 * BB_STAGE;    // 75776
// fused GRU smem: A stages | B stages | h-state
constexpr int G3_OFF_H = GSMEM;                  // 75776
constexpr int GSMEM_G3 = G3_OFF_H + 64 * 128 * 4; // 108544

// ================= GEMM-F32IN (merge1): fp32 B, register-staged convert ===========
template <int KTOT, int MTOT, int EPI, bool SPLIT>
__global__ __launch_bounds__(256, 2) void gemm_mma(
    const float* __restrict__ X0, const float* __restrict__ X1,
    const u16* __restrict__ Wh_g, const u16* __restrict__ Wl_g,
    const float* __restrict__ Bias, const float* __restrict__ Res,
    float* __restrict__ Out)
{
    extern __shared__ __align__(16) char sm[];
    const u32 sm0 = smem_u32(sm);

    const int img = blockIdx.z;
    const int p0  = blockIdx.x * 128;
    const int m0  = blockIdx.y * 128;
    const int tid = threadIdx.x;
    const int lane = tid & 31, wid = tid >> 5;
    const int wm = wid >> 2, wn = wid & 3;

    float acc[4][4][4];
#pragma unroll
    for (int i = 0; i < 4; i++)
#pragma unroll
        for (int j = 0; j < 4; j++)
#pragma unroll
            for (int q = 0; q < 4; q++) acc[i][j][q] = 0.f;

    constexpr int NCH = KTOT / KC;
    float4 breg[2][4];

    auto ldgB = [&](int c, int buf) {
        const int kbase = c * KC;
        const float* Xc = X0;
        int kb = kbase;
        if (SPLIT && kbase >= 128) { Xc = X1; kb = kbase - 128; }
        const size_t bbase = ((size_t)img * (SPLIT ? 128 : KTOT) + kb) * NPIX + p0;
#pragma unroll
        for (int i = 0; i < 4; i++) {
            int idx = tid + i * 256;
            int row = idx >> 5, seg = idx & 31;
            breg[buf][i] = *reinterpret_cast<const float4*>(
                Xc + bbase + (size_t)row * NPIX + seg * 4);
        }
    };
    auto copyA = [&](int c, int s) {
        const size_t abase = (size_t)m0 * KTOT + c * KC;
        const u32 adst = sm0 + s * A_STAGE_B;
#pragma unroll
        for (int i = 0; i < 4; i++) {
            int idx = tid + i * 256;
            int plane = idx >> 9, rem = idx & 511;
            int row = rem >> 2, seg = rem & 3;
            const u16* src = (plane ? Wl_g : Wh_g) + abase + (size_t)row * KTOT + seg * 8;
            cpasync16(adst + plane * A_PLANE_B + row * A_PITCH_B + seg * 16, src);
        }
    };

    const int lr  = lane & 7;
    const int lth = (lane >> 3) & 1;
    const int ltv = lane >> 4;
    const u32 a_row = (u32)(wm * 64 + lth * 8 + lr);

    ldgB(0, 0);
    copyA(0, 0); cp_commit();

#pragma unroll 1
    for (int c = 0; c < NCH; c++) {
        const int s = c & 1;
        if (c + 1 < NCH) ldgB(c + 1, s ^ 1);

        {
            const u32 bhoff = OFF_B0 + s * BB_STAGE;
#pragma unroll
            for (int i = 0; i < 4; i++) {
                int idx = tid + i * 256;
                int row = idx >> 5, seg = idx & 31;
                float4 v = breg[s][i];
                u32 h0, l0, h1, l1;
                split_pack(v.x, v.y, h0, l0);
                split_pack(v.z, v.w, h1, l1);
                u32 off = (u32)row * BB_PITCH + seg * 8;
                *reinterpret_cast<uint2*>(sm + bhoff + off) = make_uint2(h0, h1);
                *reinterpret_cast<uint2*>(sm + bhoff + BB_PLANE + off) = make_uint2(l0, l1);
            }
        }
        asm volatile("cp.async.wait_group 0;" ::: "memory");
        __syncthreads();

        if (c + 1 < NCH) { copyA(c + 1, s ^ 1); cp_commit(); }

        const u32 ah = sm0 + s * A_STAGE_B;
        const u32 al = ah + A_PLANE_B;
        const u32 bh = sm0 + OFF_B0 + s * BB_STAGE;
        const u32 bl = bh + BB_PLANE;

#pragma unroll
        for (int kk = 0; kk < KC / 16; kk++) {
            u32 af[4][4];
            u32 bfh[4][2], bfl[4][2];
            const u32 a_off = a_row * A_PITCH_B + kk * 32 + ltv * 16;
            const u32 b_off = (u32)(kk * 16 + lth * 8 + lr) * BB_PITCH + wn * 64 + ltv * 16;
#pragma unroll
            for (int mf = 0; mf < 4; mf++)
                ldm_x4(af[mf], ah + a_off + mf * 16 * A_PITCH_B);
#pragma unroll
            for (int nh = 0; nh < 2; nh++) {
                u32 r[4];
                ldm_x4t(r, bh + b_off + nh * 32);
                bfh[nh * 2][0] = r[0]; bfh[nh * 2][1] = r[1];
                bfh[nh * 2 + 1][0] = r[2]; bfh[nh * 2 + 1][1] = r[3];
            }
#pragma unroll
            for (int mf = 0; mf < 4; mf++)
#pragma unroll
                for (int nf = 0; nf < 4; nf++)
                    mma_bf16(acc[mf][nf], af[mf], bfh[nf]);
#pragma unroll
            for (int nh = 0; nh < 2; nh++) {
                u32 r[4];
                ldm_x4t(r, bl + b_off + nh * 32);
                bfl[nh * 2][0] = r[0]; bfl[nh * 2][1] = r[1];
                bfl[nh * 2 + 1][0] = r[2]; bfl[nh * 2 + 1][1] = r[3];
            }
#pragma unroll
            for (int mf = 0; mf < 4; mf++)
#pragma unroll
                for (int nf = 0; nf < 4; nf++)
                    mma_bf16(acc[mf][nf], af[mf], bfl[nf]);
#pragma unroll
            for (int mf = 0; mf < 4; mf++)
                ldm_x4(af[mf], al + a_off + mf * 16 * A_PITCH_B);
#pragma unroll
            for (int mf = 0; mf < 4; mf++)
#pragma unroll
                for (int nf = 0; nf < 4; nf++)
                    mma_bf16(acc[mf][nf], af[mf], bfh[nf]);
        }
    }

    const int g = lane >> 2, tg = lane & 3;
#pragma unroll
    for (int mf = 0; mf < 4; mf++) {
#pragma unroll
        for (int half = 0; half < 2; half++) {
            const int m = m0 + wm * 64 + mf * 16 + half * 8 + g;
            const float bias = Bias ? Bias[m] : 0.f;
            const size_t rowb = ((size_t)img * MTOT + m) * NPIX;
#pragma unroll
            for (int nf = 0; nf < 4; nf++) {
                const int px = p0 + wn * 32 + nf * 8 + 2 * tg;
                float v0 = acc[mf][nf][half * 2 + 0] + bias;
                float v1 = acc[mf][nf][half * 2 + 1] + bias;
                if (EPI == 1) { v0 = gelu_exact(v0); v1 = gelu_exact(v1); }
                *reinterpret_cast<float2*>(&Out[rowb + px]) = make_float2(v0, v1);
            }
        }
    }
}

// ================= GEMM-PLANES (merge2 / up): pure cp.async mainloop ==========
template <int KTOT, int MTOT, int EPI, bool OUTPL>
__global__ __launch_bounds__(256, 2) void gemm_pl(
    const u16* __restrict__ Bh_g, const u16* __restrict__ Bl_g,
    const u16* __restrict__ Wh_g, const u16* __restrict__ Wl_g,
    const float* __restrict__ Bias, const float* __restrict__ Res,
    u16* __restrict__ OutH, u16* __restrict__ OutL, float* __restrict__ OutF)
{
    extern __shared__ __align__(16) char sm[];
    const u32 sm0 = smem_u32(sm);

    const int img = blockIdx.z;
    const int p0  = blockIdx.x * 128;
    const int m0  = blockIdx.y * 128;
    const int tid = threadIdx.x;
    const int lane = tid & 31, wid = tid >> 5;
    const int wm = wid >> 2, wn = wid & 3;

    float acc[4][4][4];
#pragma unroll
    for (int i = 0; i < 4; i++)
#pragma unroll
        for (int j = 0; j < 4; j++)
#pragma unroll
            for (int q = 0; q < 4; q++) acc[i][j][q] = 0.f;

    constexpr int NCH = KTOT / KC;

    auto copyAB = [&](int c, int s) {
        const int kbase = c * KC;
        const size_t bbase = ((size_t)img * KTOT + kbase) * NPIX + p0;
#pragma unroll
        for (int i = 0; i < 4; i++) {
            int idx = tid + i * 256;
            int plane = idx >> 9, rem = idx & 511;
            int row = rem >> 4, seg = rem & 15;
            const u16* src = (plane ? Bl_g : Bh_g) + bbase + (size_t)row * NPIX + seg * 8;
            cpasync16(sm0 + OFF_B0 + s * BB_STAGE + plane * BB_PLANE
                      + row * BB_PITCH + seg * 16, src);
        }
        const size_t abase = (size_t)m0 * KTOT + kbase;
        const u32 adst = sm0 + s * A_STAGE_B;
#pragma unroll
        for (int i = 0; i < 4; i++) {
            int idx = tid + i * 256;
            int plane = idx >> 9, rem = idx & 511;
            int row = rem >> 2, seg = rem & 3;
            const u16* src = (plane ? Wl_g : Wh_g) + abase + (size_t)row * KTOT + seg * 8;
            cpasync16(adst + plane * A_PLANE_B + row * A_PITCH_B + seg * 16, src);
        }
    };

    const int lr  = lane & 7;
    const int lth = (lane >> 3) & 1;
    const int ltv = lane >> 4;
    const u32 a_row = (u32)(wm * 64 + lth * 8 + lr);

    copyAB(0, 0); cp_commit();

#pragma unroll 1
    for (int c = 0; c < NCH; c++) {
        const int s = c & 1;
        asm volatile("cp.async.wait_group 0;" ::: "memory");
        __syncthreads();

        if (c + 1 < NCH) { copyAB(c + 1, s ^ 1); cp_commit(); }

        const u32 ah = sm0 + s * A_STAGE_B;
        const u32 al = ah + A_PLANE_B;
        const u32 bh = sm0 + OFF_B0 + s * BB_STAGE;
        const u32 bl = bh + BB_PLANE;

#pragma unroll
        for (int kk = 0; kk < KC / 16; kk++) {
            u32 af[4][4];
            u32 bfh[4][2], bfl[4][2];
            const u32 a_off = a_row * A_PITCH_B + kk * 32 + ltv * 16;
            const u32 b_off = (u32)(kk * 16 + lth * 8 + lr) * BB_PITCH + wn * 64 + ltv * 16;
#pragma unroll
            for (int mf = 0; mf < 4; mf++)
                ldm_x4(af[mf], ah + a_off + mf * 16 * A_PITCH_B);
#pragma unroll
            for (int nh = 0; nh < 2; nh++) {
                u32 r[4];
                ldm_x4t(r, bh + b_off + nh * 32);
                bfh[nh * 2][0] = r[0]; bfh[nh * 2][1] = r[1];
                bfh[nh * 2 + 1][0] = r[2]; bfh[nh * 2 + 1][1] = r[3];
            }
#pragma unroll
            for (int mf = 0; mf < 4; mf++)
#pragma unroll
                for (int nf = 0; nf < 4; nf++)
                    mma_bf16(acc[mf][nf], af[mf], bfh[nf]);
#pragma unroll
            for (int nh = 0; nh < 2; nh++) {
                u32 r[4];
                ldm_x4t(r, bl + b_off + nh * 32);
                bfl[nh * 2][0] = r[0]; bfl[nh * 2][1] = r[1];
                bfl[nh * 2 + 1][0] = r[2]; bfl[nh * 2 + 1][1] = r[3];
            }
#pragma unroll
            for (int mf = 0; mf < 4; mf++)
#pragma unroll
                for (int nf = 0; nf < 4; nf++)
                    mma_bf16(acc[mf][nf], af[mf], bfl[nf]);
#pragma unroll
            for (int mf = 0; mf < 4; mf++)
                ldm_x4(af[mf], al + a_off + mf * 16 * A_PITCH_B);
#pragma unroll
            for (int mf = 0; mf < 4; mf++)
#pragma unroll
                for (int nf = 0; nf < 4; nf++)
                    mma_bf16(acc[mf][nf], af[mf], bfh[nf]);
        }
    }

    const int g = lane >> 2, tg = lane & 3;
#pragma unroll
    for (int mf = 0; mf < 4; mf++) {
#pragma unroll
        for (int half = 0; half < 2; half++) {
            const int m = m0 + wm * 64 + mf * 16 + half * 8 + g;
            const float bias = Bias ? Bias[m] : 0.f;
            const size_t rowb = ((size_t)img * MTOT + m) * NPIX;
            const float* resrow = (EPI == 2) ? &Res[((size_t)img * CDIM + m) * NPIX] : nullptr;
#pragma unroll
            for (int nf = 0; nf < 4; nf++) {
                const int px = p0 + wn * 32 + nf * 8 + 2 * tg;
                float v0 = acc[mf][nf][half * 2 + 0] + bias;
                float v1 = acc[mf][nf][half * 2 + 1] + bias;
                if (EPI == 2) { v0 += resrow[px]; v1 += resrow[px + 1]; }
                if (OUTPL) {
                    u32 hi, lo;
                    split_pack(v0, v1, hi, lo);
                    const size_t hw = (rowb + px) >> 1;
                    reinterpret_cast<u32*>(OutH)[hw] = hi;
                    reinterpret_cast<u32*>(OutL)[hw] = lo;
                } else {
                    *reinterpret_cast<float2*>(&OutF[rowb + px]) = make_float2(v0, v1);
                }
            }
        }
    }
}

// ================= fused GRU v3: M=128 x N=128, A/B streamed, scan in epilogue ======
// Weight rows interleaved: row 2c = W_hidden[c], row 2c+1 = W_gate[c]. my in {0,1}.
// OUTPL: write g planes; else fp32.
template <bool OUTPL>
__global__ __launch_bounds__(256, 2) void gru_fused3(
    const u16* __restrict__ Bh_g, const u16* __restrict__ Bl_g,
    const u16* __restrict__ Wh_g, const u16* __restrict__ Wl_g,
    u16* __restrict__ OutH, u16* __restrict__ OutL, float* __restrict__ OutF)
{
    extern __shared__ __align__(16) char sm[];
    const u32 sm0 = smem_u32(sm);

    const int b   = blockIdx.z;
    const int p0  = blockIdx.x * 128;
    const int my  = blockIdx.y;
    const int m0  = my * 128;
    const int tid = threadIdx.x;
    const int lane = tid & 31, wid = tid >> 5;
    const int wm = wid >> 2, wn = wid & 3;
    const int lr = lane & 7, lth = (lane >> 3) & 1, ltv = lane >> 4;
    const int g  = lane >> 2, tg = lane & 3;
    const u32 a_row = (u32)(wm * 64 + lth * 8 + lr);

    // zero h state (64 ch x 128 px fp32)
    for (int i = tid; i < 64 * 128 / 4; i += 256)
        reinterpret_cast<float4*>(sm + G3_OFF_H)[i] = make_float4(0.f, 0.f, 0.f, 0.f);

    float acc[4][4][4];
#pragma unroll
    for (int i = 0; i < 4; i++)
#pragma unroll
        for (int j = 0; j < 4; j++)
#pragma unroll
            for (int q = 0; q < 4; q++) acc[i][j][q] = 0.f;

    auto copyAB = [&](int it, int s) {
        const int v = it >> 2, c = it & 3;
        // B planes: X[b*NV+v][c*32 .. +32][p0 .. +128]
        const size_t bbase = ((size_t)(b * NV + v) * 128 + c * KC) * NPIX + p0;
#pragma unroll
        for (int i = 0; i < 4; i++) {
            int idx = tid + i * 256;
            int plane = idx >> 9, rem = idx & 511;
            int row = rem >> 4, seg = rem & 15;
            const u16* src = (plane ? Bl_g : Bh_g) + bbase + (size_t)row * NPIX + seg * 8;
            cpasync16(sm0 + OFF_B0 + s * BB_STAGE + plane * BB_PLANE
                      + row * BB_PITCH + seg * 16, src);
        }
        // A planes: W[m0 .. +128][c*32 .. +32]
        const size_t abase = (size_t)m0 * 128 + c * KC;
        const u32 adst = sm0 + s * A_STAGE_B;
#pragma unroll
        for (int i = 0; i < 4; i++) {
            int idx = tid + i * 256;
            int plane = idx >> 9, rem = idx & 511;
            int row = rem >> 2, seg = rem & 3;
            const u16* src = (plane ? Wl_g : Wh_g) + abase + (size_t)row * 128 + seg * 8;
            cpasync16(adst + plane * A_PLANE_B + row * A_PITCH_B + seg * 16, src);
        }
    };

    copyAB(0, 0); cp_commit();
    __syncthreads();  // h-zeroing complete before epilogue use (also orders first stage)

#pragma unroll 1
    for (int it = 0; it < 4 * NV; it++) {
        const int s = it & 1;
        asm volatile("cp.async.wait_group 0;" ::: "memory");
        __syncthreads();   // MMA(it-1) reads of stage s^1 done; stage s visible

        if (it + 1 < 4 * NV) { copyAB(it + 1, s ^ 1); cp_commit(); }

        const u32 ah = sm0 + s * A_STAGE_B;
        const u32 al = ah + A_PLANE_B;
        const u32 bh = sm0 + OFF_B0 + s * BB_STAGE;
        const u32 bl = bh + BB_PLANE;

#pragma unroll
        for (int kk = 0; kk < KC / 16; kk++) {
            u32 af[4][4];
            u32 bfh[4][2], bfl[4][2];
            const u32 a_off = a_row * A_PITCH_B + kk * 32 + ltv * 16;
            const u32 b_off = (u32)(kk * 16 + lth * 8 + lr) * BB_PITCH + wn * 64 + ltv * 16;
#pragma unroll
            for (int mf = 0; mf < 4; mf++)
                ldm_x4(af[mf], ah + a_off + mf * 16 * A_PITCH_B);
#pragma unroll
            for (int nh = 0; nh < 2; nh++) {
                u32 r[4];
                ldm_x4t(r, bh + b_off + nh * 32);
                bfh[nh * 2][0] = r[0]; bfh[nh * 2][1] = r[1];
                bfh[nh * 2 + 1][0] = r[2]; bfh[nh * 2 + 1][1] = r[3];
            }
#pragma unroll
            for (int mf = 0; mf < 4; mf++)
#pragma unroll
                for (int nf = 0; nf < 4; nf++)
                    mma_bf16(acc[mf][nf], af[mf], bfh[nf]);
#pragma unroll
            for (int nh = 0; nh < 2; nh++) {
                u32 r[4];
                ldm_x4t(r, bl + b_off + nh * 32);
                bfl[nh * 2][0] = r[0]; bfl[nh * 2][1] = r[1];
                bfl[nh * 2 + 1][0] = r[2]; bfl[nh * 2 + 1][1] = r[3];
            }
#pragma unroll
            for (int mf = 0; mf < 4; mf++)
#pragma unroll
                for (int nf = 0; nf < 4; nf++)
                    mma_bf16(acc[mf][nf], af[mf], bfl[nf]);
#pragma unroll
            for (int mf = 0; mf < 4; mf++)
                ldm_x4(af[mf], al + a_off + mf * 16 * A_PITCH_B);
#pragma unroll
            for (int mf = 0; mf < 4; mf++)
#pragma unroll
                for (int nf = 0; nf < 4; nf++)
                    mma_bf16(acc[mf][nf], af[mf], bfh[nf]);
        }

        // end of view: scan epilogue (verified shfl mapping)
        if ((it & 3) == 3) {
            const int v = it >> 2;
#pragma unroll
            for (int mf = 0; mf < 4; mf++) {
#pragma unroll
                for (int nf = 0; nf < 4; nf++) {
#pragma unroll
                    for (int half = 0; half < 2; half++) {
                        float a0 = acc[mf][nf][half * 2 + 0];
                        float a1 = acc[mf][nf][half * 2 + 1];
                        float b0 = __shfl_xor_sync(0xffffffffu, a0, 4);
                        float b1 = __shfl_xor_sync(0xffffffffu, a1, 4);
                        if (!(g & 1)) {   // hidden-parity lanes own channel cl
                            int row = wm * 64 + mf * 16 + half * 8 + g;
                            int cl = row >> 1;              // 0..63 within tile
                            int pxl = wn * 32 + nf * 8 + 2 * tg;
                            float2* hp = reinterpret_cast<float2*>(
                                sm + G3_OFF_H + (cl * 128 + pxl) * 4);
                            float2 h = *hp;
                            float z0 = 1.f / (1.f + expf(-b0));
                            float ht0 = (a0 >= 0.f) ? (a0 + 0.5f) : (1.f / (1.f + expf(-a0)));
                            h.x = (1.f - z0) * h.x + z0 * ht0;
                            float z1 = 1.f / (1.f + expf(-b1));
                            float ht1 = (a1 >= 0.f) ? (a1 + 0.5f) : (1.f / (1.f + expf(-a1)));
                            h.y = (1.f - z1) * h.y + z1 * ht1;
                            *hp = h;
                            const size_t d = ((size_t)(b * NV + v) * 128 + my * 64 + cl) * NPIX
                                             + p0 + pxl;
                            if (OUTPL) {
                                u32 hi, lo;
                                split_pack(h.x, h.y, hi, lo);
                                reinterpret_cast<u32*>(OutH)[d >> 1] = hi;
                                reinterpret_cast<u32*>(OutL)[d >> 1] = lo;
                            } else {
                                *reinterpret_cast<float2*>(&OutF[d]) = h;
                            }
                        }
                        acc[mf][nf][half * 2 + 0] = 0.f;
                        acc[mf][nf][half * 2 + 1] = 0.f;
                    }
                }
            }
        }
    }
}

// ---------------- fused weight prep (GRU rows interleaved) ----------------
__global__ void prep_w_all(
    const float* __restrict__ w1, const float* __restrict__ w2,
    const float* __restrict__ wg, const float* __restrict__ wgb,
    const float* __restrict__ wup,
    u16* __restrict__ w1h, u16* __restrict__ w1l,
    u16* __restrict__ w2h, u16* __restrict__ w2l,
    u16* __restrict__ wgh, u16* __restrict__ wgl,
    u16* __restrict__ wgbh, u16* __restrict__ wgbl,
    u16* __restrict__ wuph, u16* __restrict__ wupl)
{
    int i = blockIdx.x * 256 + threadIdx.x;
    float v; u16 *dh, *dl; int off;
    if      (i < 32768)  { off = i;          v = w1[off];  dh = w1h;  dl = w1l; }
    else if (i < 49152)  { off = i - 32768;  v = w2[off];  dh = w2h;  dl = w2l; }
    else if (i < 81920)  { off = i - 49152;
        int r = off >> 7, k = off & 127;
        int sr = (r & 1) ? 128 + (r >> 1) : (r >> 1);
        v = wg[sr * 128 + k]; dh = wgh; dl = wgl; }
    else if (i < 114688) { off = i - 81920;
        int r = off >> 7, k = off & 127;
        int sr = (r & 1) ? 128 + (r >> 1) : (r >> 1);
        v = wgb[sr * 128 + k]; dh = wgbh; dl = wgbl; }
    else                 { off = i - 114688; v = wup[off]; dh = wuph; dl = wupl; }
    float hf = __bfloat162float(__float2bfloat16(v));
    dh[off] = (u16)(__float_as_uint(hf) >> 16);
    dl[off] = (u16)(__float_as_uint(__bfloat162float(__float2bfloat16(v - hf))) >> 16);
}

// ---------------- depthwise 3x3 + bias + GELU: fp32 in, planes out ----------------
__global__ __launch_bounds__(256) void dw3x3_pl(
    const float* __restrict__ in, const float* __restrict__ wd,
    const float* __restrict__ bd, u16* __restrict__ outH, u16* __restrict__ outL)
{
    int c = blockIdx.y, img = blockIdx.z;
    int pix0 = (blockIdx.x * 256 + threadIdx.x) * 2;
    int h = pix0 >> 7, w0 = pix0 & 127;
    const size_t base = ((size_t)img * CDIM + c) * NPIX;
    const float* p = in + base;
    float wreg[9];
#pragma unroll
    for (int i = 0; i < 9; i++) wreg[i] = wd[c * 9 + i];
    float s0 = bd[c], s1 = bd[c];
#pragma unroll
    for (int ky = 0; ky < 3; ky++) {
        int hh = h + ky - 1;
        if ((unsigned)hh >= 128u) continue;
#pragma unroll
        for (int kx = 0; kx < 3; kx++) {
            int w_a = w0 + kx - 1;
            int w_b = w0 + 1 + kx - 1;
            if ((unsigned)w_a < 128u) s0 = fmaf(wreg[ky * 3 + kx], p[hh * WW + w_a], s0);
            if ((unsigned)w_b < 128u) s1 = fmaf(wreg[ky * 3 + kx], p[hh * WW + w_b], s1);
        }
    }
    u32 hi, lo;
    split_pack(gelu_exact(s0), gelu_exact(s1), hi, lo);
    reinterpret_cast<u32*>(outH)[(base + pix0) >> 1] = hi;
    reinterpret_cast<u32*>(outL)[(base + pix0) >> 1] = lo;
}

// ---------------- alpha: 3x3 conv C->1 (fp32 in) ----------------
__global__ __launch_bounds__(256) void alpha_conv(
    const float* __restrict__ g2, const float* __restrict__ aw,
    const float* __restrict__ ab, float* __restrict__ alpha)
{
    __shared__ float w[1152];
    for (int i = threadIdx.x; i < 1152; i += 256) w[i] = aw[i];
    __syncthreads();
    int img = blockIdx.z;
    int pix = blockIdx.x * 256 + threadIdx.x;
    int h = pix >> 7, x = pix & 127;
    float s = ab[0];
    const float* base = g2 + (size_t)img * CDIM * NPIX;
    for (int c = 0; c < CDIM; c++) {
        const float* p  = base + (size_t)c * NPIX;
        const float* wc = w + c * 9;
#pragma unroll
        for (int ky = 0; ky < 3; ky++) {
            int hh = h + ky - 1;
            if ((unsigned)hh >= 128u) continue;
#pragma unroll
            for (int kx = 0; kx < 3; kx++) {
                int ww = x + kx - 1;
                if ((unsigned)ww >= 128u) continue;
                s = fmaf(wc[ky * 3 + kx], p[hh * WW + ww], s);
            }
        }
    }
    alpha[(size_t)img * NPIX + pix] = s;
}

// ---------------- softmax pool (fp32 in, planes out) ----------------
__global__ __launch_bounds__(256) void pool_k4pl(
    const float* __restrict__ g2, const float* __restrict__ alpha,
    u16* __restrict__ outH, u16* __restrict__ outL)
{
    int b = blockIdx.z;
    int pix0 = (blockIdx.x * 256 + threadIdx.x) * 4;
    float4 a[NV];
    float4 mx = make_float4(-1e30f, -1e30f, -1e30f, -1e30f);
#pragma unroll
    for (int v = 0; v < NV; v++) {
        a[v] = *reinterpret_cast<const float4*>(&alpha[(size_t)(b * NV + v) * NPIX + pix0]);
        mx.x = fmaxf(mx.x, a[v].x); mx.y = fmaxf(mx.y, a[v].y);
        mx.z = fmaxf(mx.z, a[v].z); mx.w = fmaxf(mx.w, a[v].w);
    }
    float4 sum = make_float4(0.f, 0.f, 0.f, 0.f);
#pragma unroll
    for (int v = 0; v < NV; v++) {
        a[v].x = expf(a[v].x - mx.x); sum.x += a[v].x;
        a[v].y = expf(a[v].y - mx.y); sum.y += a[v].y;
        a[v].z = expf(a[v].z - mx.z); sum.z += a[v].z;
        a[v].w = expf(a[v].w - mx.w); sum.w += a[v].w;
    }
    float4 inv = make_float4(1.f / sum.x, 1.f / sum.y, 1.f / sum.z, 1.f / sum.w);
#pragma unroll
    for (int v = 0; v < NV; v++) {
        a[v].x *= inv.x; a[v].y *= inv.y; a[v].z *= inv.z; a[v].w *= inv.w;
    }
    for (int c = 0; c < CDIM; c++) {
        float4 s = make_float4(0.f, 0.f, 0.f, 0.f);
#pragma unroll
        for (int v = 0; v < NV; v++) {
            float4 gv = *reinterpret_cast<const float4*>(
                &g2[(((size_t)(b * NV + v)) * CDIM + c) * NPIX + pix0]);
            s.x = fmaf(a[v].x, gv.x, s.x);
            s.y = fmaf(a[v].y, gv.y, s.y);
            s.z = fmaf(a[v].z, gv.z, s.z);
            s.w = fmaf(a[v].w, gv.w, s.w);
        }
        size_t d = ((size_t)b * CDIM + c) * NPIX + pix0;
        u32 h0, l0, h1, l1;
        split_pack(s.x, s.y, h0, l0);
        split_pack(s.z, s.w, h1, l1);
        *reinterpret_cast<uint2*>(&outH[d]) = make_uint2(h0, h1);
        *reinterpret_cast<uint2*>(&outL[d]) = make_uint2(l0, l1);
    }
}

// ---------------- pixel-shuffle(4) + 3x3 conv 8->3 (512->512 resize = identity) --------
__global__ __launch_bounds__(256) void outc_k(
    const float* __restrict__ u, const float* __restrict__ wt,
    const float* __restrict__ bs, float* __restrict__ out)
{
    __shared__ float w[216];
    if (threadIdx.x < 216) w[threadIdx.x] = wt[threadIdx.x];
    __syncthreads();
    int b = blockIdx.z, co = blockIdx.y;
    int idx = blockIdx.x * 256 + threadIdx.x;
    int y = idx >> 9, x = idx & 511;
    float s = bs[co];
    const float* ub = u + (size_t)b * CDIM * NPIX;
#pragma unroll
    for (int ky = 0; ky < 3; ky++) {
        int yy = y + ky - 1;
        if ((unsigned)yy >= 512u) continue;
        int sy = yy & 3, hy = yy >> 2;
#pragma unroll
        for (int kx = 0; kx < 3; kx++) {
            int xx = x + kx - 1;
            if ((unsigned)xx >= 512u) continue;
            int sx = xx & 3, hx = xx >> 2;
            const float* up = ub + (size_t)(sy * 4 + sx) * NPIX + hy * WW + hx;
#pragma unroll
            for (int ci = 0; ci < 8; ci++)
                s = fmaf(w[(co * 8 + ci) * 9 + ky * 3 + kx], up[(size_t)ci * 16 * NPIX], s);
        }
    }
    out[((size_t)b * 3 + co) * (512 * 512) + idx] = s;
}

// ---------------- launch ----------------
extern "C" void kernel_launch(void* const* d_in, const int* in_sizes, int n_in,
                              void* d_out, int out_size)
{
    const float* feats     = (const float*)d_in[0];
    const float* prj       = (const float*)d_in[1];
    const float* merge_w1  = (const float*)d_in[2];
    const float* merge_b1  = (const float*)d_in[3];
    const float* merge_wd  = (const float*)d_in[4];
    const float* merge_bd  = (const float*)d_in[5];
    const float* merge_w2  = (const float*)d_in[6];
    const float* merge_b2  = (const float*)d_in[7];
    const float* gru_w     = (const float*)d_in[8];
    const float* gru_bw    = (const float*)d_in[9];
    const float* alpha_w   = (const float*)d_in[10];
    const float* alpha_b   = (const float*)d_in[11];
    const float* up_w      = (const float*)d_in[12];
    const float* up_b      = (const float*)d_in[13];
    const float* outc_w    = (const float*)d_in[14];
    const float* outc_b    = (const float*)d_in[15];

    float *bufA, *bufB, *alp, *u;
    u16 *dwh, *dwl, *m2h, *m2l, *g1h, *g1l, *plh, *pll;
    u16 *wm1h, *wm1l, *wm2h, *wm2l, *wgh, *wgl, *wgbh, *wgbl, *wuph, *wupl;
    cudaGetSymbolAddress((void**)&bufA, g_bufA);
    cudaGetSymbolAddress((void**)&bufB, g_bufB);
    cudaGetSymbolAddress((void**)&alp,  g_alp);
    cudaGetSymbolAddress((void**)&u,    g_u);
    cudaGetSymbolAddress((void**)&dwh,  g_dwh);  cudaGetSymbolAddress((void**)&dwl,  g_dwl);
    cudaGetSymbolAddress((void**)&m2h,  g_m2h);  cudaGetSymbolAddress((void**)&m2l,  g_m2l);
    cudaGetSymbolAddress((void**)&g1h,  g_g1h);  cudaGetSymbolAddress((void**)&g1l,  g_g1l);
    cudaGetSymbolAddress((void**)&plh,  g_plh);  cudaGetSymbolAddress((void**)&pll,  g_pll);
    cudaGetSymbolAddress((void**)&wm1h, g_wm1h); cudaGetSymbolAddress((void**)&wm1l, g_wm1l);
    cudaGetSymbolAddress((void**)&wm2h, g_wm2h); cudaGetSymbolAddress((void**)&wm2l, g_wm2l);
    cudaGetSymbolAddress((void**)&wgh,  g_wgh);  cudaGetSymbolAddress((void**)&wgl,  g_wgl);
    cudaGetSymbolAddress((void**)&wgbh, g_wgbh); cudaGetSymbolAddress((void**)&wgbl, g_wgbl);
    cudaGetSymbolAddress((void**)&wuph, g_wuph); cudaGetSymbolAddress((void**)&wupl, g_wupl);

    cudaFuncSetAttribute(gemm_mma<256, 128, 1, true >, cudaFuncAttributeMaxDynamicSharedMemorySize, GSMEM);
    cudaFuncSetAttribute(gemm_pl<128, 128, 2, true >,  cudaFuncAttributeMaxDynamicSharedMemorySize, GSMEM);
    cudaFuncSetAttribute(gemm_pl<128, 128, 0, false>,  cudaFuncAttributeMaxDynamicSharedMemorySize, GSMEM);
    cudaFuncSetAttribute(gru_fused3<true >, cudaFuncAttributeMaxDynamicSharedMemorySize, GSMEM_G3);
    cudaFuncSetAttribute(gru_fused3<false>, cudaFuncAttributeMaxDynamicSharedMemorySize, GSMEM_G3);

    prep_w_all<<<512, 256>>>(merge_w1, merge_w2, gru_w, gru_bw, up_w,
                             wm1h, wm1l, wm2h, wm2l, wgh, wgl, wgbh, wgbl, wuph, wupl);

    // merge1: 1x1 (2C->C) + GELU (fp32 out)
    gemm_mma<256, 128, 1, true ><<<dim3(128, 1, BVI), 256, GSMEM>>>(
        feats, prj, wm1h, wm1l, merge_b1, nullptr, bufA);
    // depthwise 3x3 + GELU -> planes
    dw3x3_pl<<<dim3(32, CDIM, BVI), 256>>>(bufA, merge_wd, merge_bd, dwh, dwl);
    // merge2: planes in, bias + residual(feats), planes out
    gemm_pl<128, 128, 2, true ><<<dim3(128, 1, BVI), 256, GSMEM>>>(
        dwh, dwl, wm2h, wm2l, merge_b2, feats, m2h, m2l, nullptr);
    // fused fwd GRU (linear + scan) -> g1 planes
    gru_fused3<true ><<<dim3(NPIX / 128, 2, NB), 256, GSMEM_G3>>>(
        m2h, m2l, wgh, wgl, g1h, g1l, nullptr);
    // fused bwd GRU (H-flips cancel -> forward scan) -> g2 fp32
    gru_fused3<false><<<dim3(NPIX / 128, 2, NB), 256, GSMEM_G3>>>(
        g1h, g1l, wgbh, wgbl, nullptr, nullptr, bufB);
    // alpha conv + softmax pool (fp32 in, planes out)
    alpha_conv<<<dim3(64, 1, BVI), 256>>>(bufB, alpha_w, alpha_b, alp);
    pool_k4pl<<<dim3(16, 1, NB), 256>>>(bufB, alp, plh, pll);
    // up: planes in, fp32 out
    gemm_pl<128, 128, 0, false><<<dim3(128, 1, NB), 256, GSMEM>>>(
        plh, pll, wuph, wupl, up_b, nullptr, nullptr, nullptr, u);
    // pixel shuffle + outc 3x3
    outc_k<<<dim3(1024, 3, NB), 256>>>(u, outc_w, outc_b, (float*)d_out);
}

// round 14
// speedup vs baseline: 1.2163x; 1.2163x over previous
#include <cuda_runtime.h>
#include <cuda_bf16.h>
#include <math.h>
#include <stdint.h>

#define NPIX 16384
#define CDIM 128
#define NB 2
#define NV 6
#define BVI 12
#define WW 128

typedef uint16_t u16;
typedef uint32_t u32;

// ---------------- scratch ----------------
__device__ float g_bufA[(size_t)BVI * CDIM * NPIX];     // merge1 out (fp32)
__device__ float g_bufB[(size_t)BVI * CDIM * NPIX];     // g2 (fp32)
__device__ float g_hg  [(size_t)BVI * 2 * CDIM * NPIX]; // GRU linear out (fp32)
__device__ float g_alp [(size_t)BVI * NPIX];
__device__ float g_u   [(size_t)NB * CDIM * NPIX];
// bf16 hi/lo planes
__device__ __align__(16) u16 g_dwh [(size_t)BVI * CDIM * NPIX], g_dwl [(size_t)BVI * CDIM * NPIX];
__device__ __align__(16) u16 g_m2h [(size_t)BVI * CDIM * NPIX], g_m2l [(size_t)BVI * CDIM * NPIX];
__device__ __align__(16) u16 g_g1h [(size_t)BVI * CDIM * NPIX], g_g1l [(size_t)BVI * CDIM * NPIX];
__device__ __align__(16) u16 g_plh [(size_t)NB * CDIM * NPIX],  g_pll [(size_t)NB * CDIM * NPIX];
// weight hi/lo planes (k-major rows)
__device__ __align__(16) u16 g_wm1h[128 * 256], g_wm1l[128 * 256];
__device__ __align__(16) u16 g_wm2h[128 * 128], g_wm2l[128 * 128];
__device__ __align__(16) u16 g_wgh [256 * 128], g_wgl [256 * 128];
__device__ __align__(16) u16 g_wgbh[256 * 128], g_wgbl[256 * 128];
__device__ __align__(16) u16 g_wuph[128 * 128], g_wupl[128 * 128];

__device__ __forceinline__ float gelu_exact(float x) {
    return 0.5f * x * (1.0f + erff(x * 0.70710678118654752f));
}
__device__ __forceinline__ u32 smem_u32(const void* p) {
    return (u32)__cvta_generic_to_shared(p);
}
__device__ __forceinline__ void split_pack(float v0, float v1, u32& hi, u32& lo) {
    asm("cvt.rn.bf16x2.f32 %0, %1, %2;" : "=r"(hi) : "f"(v1), "f"(v0));
    float r0 = v0 - __uint_as_float(hi << 16);
    float r1 = v1 - __uint_as_float(hi & 0xffff0000u);
    asm("cvt.rn.bf16x2.f32 %0, %1, %2;" : "=r"(lo) : "f"(r1), "f"(r0));
}
__device__ __forceinline__ void ldm_x4(u32* r, u32 addr) {
    asm volatile("ldmatrix.sync.aligned.m8n8.x4.shared.b16 {%0,%1,%2,%3}, [%4];"
                 : "=r"(r[0]), "=r"(r[1]), "=r"(r[2]), "=r"(r[3]) : "r"(addr));
}
__device__ __forceinline__ void ldm_x4t(u32* r, u32 addr) {
    asm volatile("ldmatrix.sync.aligned.m8n8.x4.trans.shared.b16 {%0,%1,%2,%3}, [%4];"
                 : "=r"(r[0]), "=r"(r[1]), "=r"(r[2]), "=r"(r[3]) : "r"(addr));
}
__device__ __forceinline__ void mma_bf16(float* d, const u32* a, const u32* b) {
    asm volatile(
        "mma.sync.aligned.m16n8k16.row.col.f32.bf16.bf16.f32 "
        "{%0,%1,%2,%3}, {%4,%5,%6,%7}, {%8,%9}, {%0,%1,%2,%3};"
        : "+f"(d[0]), "+f"(d[1]), "+f"(d[2]), "+f"(d[3])
        : "r"(a[0]), "r"(a[1]), "r"(a[2]), "r"(a[3]), "r"(b[0]), "r"(b[1]));
}
__device__ __forceinline__ void cpasync16(u32 dst, const void* src) {
    asm volatile("cp.async.cg.shared.global [%0], [%1], 16;" :: "r"(dst), "l"(src));
}
__device__ __forceinline__ void cp_commit() {
    asm volatile("cp.async.commit_group;" ::: "memory");
}

// ---------------- tile constants ----------------
constexpr int KC = 32;
// streamed-A path (merge1 only)
constexpr int A_PITCH_B = 80;
constexpr int A_PLANE_B = 128 * A_PITCH_B;       // 10240
constexpr int A_STAGE_B = 2 * A_PLANE_B;         // 20480
constexpr int BB_PITCH = 272;
constexpr int BB_PLANE = KC * BB_PITCH;          // 8704
constexpr int BB_STAGE = 2 * BB_PLANE;           // 17408
constexpr int OFF_B0 = 2 * A_STAGE_B;            // 40960
constexpr int GSMEM  = OFF_B0 + 2 * BB_STAGE;    // 75776
// resident-A path (KTOT=128 plane GEMMs)
constexpr int AR_PITCH = 272;                    // 128 k * 2B + 16 pad
constexpr int AR_PLANE = 128 * AR_PITCH;         // 34816 per plane
constexpr int R_OFF_B0 = 2 * AR_PLANE;           // 69632
constexpr int GSMEM_R  = R_OFF_B0 + 2 * BB_STAGE; // 104448

// ================= GEMM-F32IN (merge1): fp32 B, register-staged convert ===========
template <int KTOT, int MTOT, int EPI, bool SPLIT>
__global__ __launch_bounds__(256, 2) void gemm_mma(
    const float* __restrict__ X0, const float* __restrict__ X1,
    const u16* __restrict__ Wh_g, const u16* __restrict__ Wl_g,
    const float* __restrict__ Bias, const float* __restrict__ Res,
    float* __restrict__ Out)
{
    extern __shared__ __align__(16) char sm[];
    const u32 sm0 = smem_u32(sm);

    const int img = blockIdx.z;
    const int p0  = blockIdx.x * 128;
    const int m0  = blockIdx.y * 128;
    const int tid = threadIdx.x;
    const int lane = tid & 31, wid = tid >> 5;
    const int wm = wid >> 2, wn = wid & 3;

    float acc[4][4][4];
#pragma unroll
    for (int i = 0; i < 4; i++)
#pragma unroll
        for (int j = 0; j < 4; j++)
#pragma unroll
            for (int q = 0; q < 4; q++) acc[i][j][q] = 0.f;

    constexpr int NCH = KTOT / KC;
    float4 breg[2][4];

    auto ldgB = [&](int c, int buf) {
        const int kbase = c * KC;
        const float* Xc = X0;
        int kb = kbase;
        if (SPLIT && kbase >= 128) { Xc = X1; kb = kbase - 128; }
        const size_t bbase = ((size_t)img * (SPLIT ? 128 : KTOT) + kb) * NPIX + p0;
#pragma unroll
        for (int i = 0; i < 4; i++) {
            int idx = tid + i * 256;
            int row = idx >> 5, seg = idx & 31;
            breg[buf][i] = *reinterpret_cast<const float4*>(
                Xc + bbase + (size_t)row * NPIX + seg * 4);
        }
    };
    auto copyA = [&](int c, int s) {
        const size_t abase = (size_t)m0 * KTOT + c * KC;
        const u32 adst = sm0 + s * A_STAGE_B;
#pragma unroll
        for (int i = 0; i < 4; i++) {
            int idx = tid + i * 256;
            int plane = idx >> 9, rem = idx & 511;
            int row = rem >> 2, seg = rem & 3;
            const u16* src = (plane ? Wl_g : Wh_g) + abase + (size_t)row * KTOT + seg * 8;
            cpasync16(adst + plane * A_PLANE_B + row * A_PITCH_B + seg * 16, src);
        }
    };

    const int lr  = lane & 7;
    const int lth = (lane >> 3) & 1;
    const int ltv = lane >> 4;
    const u32 a_row = (u32)(wm * 64 + lth * 8 + lr);

    ldgB(0, 0);
    copyA(0, 0); cp_commit();

#pragma unroll 1
    for (int c = 0; c < NCH; c++) {
        const int s = c & 1;
        if (c + 1 < NCH) ldgB(c + 1, s ^ 1);

        {
            const u32 bhoff = OFF_B0 + s * BB_STAGE;
#pragma unroll
            for (int i = 0; i < 4; i++) {
                int idx = tid + i * 256;
                int row = idx >> 5, seg = idx & 31;
                float4 v = breg[s][i];
                u32 h0, l0, h1, l1;
                split_pack(v.x, v.y, h0, l0);
                split_pack(v.z, v.w, h1, l1);
                u32 off = (u32)row * BB_PITCH + seg * 8;
                *reinterpret_cast<uint2*>(sm + bhoff + off) = make_uint2(h0, h1);
                *reinterpret_cast<uint2*>(sm + bhoff + BB_PLANE + off) = make_uint2(l0, l1);
            }
        }
        asm volatile("cp.async.wait_group 0;" ::: "memory");
        __syncthreads();

        if (c + 1 < NCH) { copyA(c + 1, s ^ 1); cp_commit(); }

        const u32 ah = sm0 + s * A_STAGE_B;
        const u32 al = ah + A_PLANE_B;
        const u32 bh = sm0 + OFF_B0 + s * BB_STAGE;
        const u32 bl = bh + BB_PLANE;

#pragma unroll
        for (int kk = 0; kk < KC / 16; kk++) {
            u32 af[4][4];
            u32 bfh[4][2], bfl[4][2];
            const u32 a_off = a_row * A_PITCH_B + kk * 32 + ltv * 16;
            const u32 b_off = (u32)(kk * 16 + lth * 8 + lr) * BB_PITCH + wn * 64 + ltv * 16;
#pragma unroll
            for (int mf = 0; mf < 4; mf++)
                ldm_x4(af[mf], ah + a_off + mf * 16 * A_PITCH_B);
#pragma unroll
            for (int nh = 0; nh < 2; nh++) {
                u32 r[4];
                ldm_x4t(r, bh + b_off + nh * 32);
                bfh[nh * 2][0] = r[0]; bfh[nh * 2][1] = r[1];
                bfh[nh * 2 + 1][0] = r[2]; bfh[nh * 2 + 1][1] = r[3];
            }
#pragma unroll
            for (int mf = 0; mf < 4; mf++)
#pragma unroll
                for (int nf = 0; nf < 4; nf++)
                    mma_bf16(acc[mf][nf], af[mf], bfh[nf]);
#pragma unroll
            for (int nh = 0; nh < 2; nh++) {
                u32 r[4];
                ldm_x4t(r, bl + b_off + nh * 32);
                bfl[nh * 2][0] = r[0]; bfl[nh * 2][1] = r[1];
                bfl[nh * 2 + 1][0] = r[2]; bfl[nh * 2 + 1][1] = r[3];
            }
#pragma unroll
            for (int mf = 0; mf < 4; mf++)
#pragma unroll
                for (int nf = 0; nf < 4; nf++)
                    mma_bf16(acc[mf][nf], af[mf], bfl[nf]);
#pragma unroll
            for (int mf = 0; mf < 4; mf++)
                ldm_x4(af[mf], al + a_off + mf * 16 * A_PITCH_B);
#pragma unroll
            for (int mf = 0; mf < 4; mf++)
#pragma unroll
                for (int nf = 0; nf < 4; nf++)
                    mma_bf16(acc[mf][nf], af[mf], bfh[nf]);
        }
    }

    const int g = lane >> 2, tg = lane & 3;
#pragma unroll
    for (int mf = 0; mf < 4; mf++) {
#pragma unroll
        for (int half = 0; half < 2; half++) {
            const int m = m0 + wm * 64 + mf * 16 + half * 8 + g;
            const float bias = Bias ? Bias[m] : 0.f;
            const size_t rowb = ((size_t)img * MTOT + m) * NPIX;
#pragma unroll
            for (int nf = 0; nf < 4; nf++) {
                const int px = p0 + wn * 32 + nf * 8 + 2 * tg;
                float v0 = acc[mf][nf][half * 2 + 0] + bias;
                float v1 = acc[mf][nf][half * 2 + 1] + bias;
                if (EPI == 1) { v0 = gelu_exact(v0); v1 = gelu_exact(v1); }
                *reinterpret_cast<float2*>(&Out[rowb + px]) = make_float2(v0, v1);
            }
        }
    }
}

// ================= GEMM-PLANES resident-A (KTOT=128): pure cp.async B pipeline ======
template <int MTOT, int EPI, bool OUTPL>
__global__ __launch_bounds__(256, 2) void gemm_pl(
    const u16* __restrict__ Bh_g, const u16* __restrict__ Bl_g,
    const u16* __restrict__ Wh_g, const u16* __restrict__ Wl_g,
    const float* __restrict__ Bias, const float* __restrict__ Res,
    u16* __restrict__ OutH, u16* __restrict__ OutL, float* __restrict__ OutF)
{
    extern __shared__ __align__(16) char sm[];
    const u32 sm0 = smem_u32(sm);

    const int img = blockIdx.z;
    const int p0  = blockIdx.x * 128;
    const int m0  = blockIdx.y * 128;
    const int tid = threadIdx.x;
    const int lane = tid & 31, wid = tid >> 5;
    const int wm = wid >> 2, wn = wid & 3;

    float acc[4][4][4];
#pragma unroll
    for (int i = 0; i < 4; i++)
#pragma unroll
        for (int j = 0; j < 4; j++)
#pragma unroll
            for (int q = 0; q < 4; q++) acc[i][j][q] = 0.f;

    constexpr int NCH = 128 / KC;   // 4

    // resident A: 128 rows x 128 k, hi+lo (one-time)
    {
        const size_t abase = (size_t)m0 * 128;
#pragma unroll
        for (int i = 0; i < 16; i++) {
            int idx = tid + i * 256;              // 0..4095
            int plane = idx >> 11, rem = idx & 2047;
            int row = rem >> 4, seg = rem & 15;   // 128 rows x 16 segs(16B)
            const u16* src = (plane ? Wl_g : Wh_g) + abase + (size_t)row * 128 + seg * 8;
            cpasync16(sm0 + plane * AR_PLANE + row * AR_PITCH + seg * 16, src);
        }
        cp_commit();
    }

    auto copyB = [&](int c, int s) {
        const size_t bbase = ((size_t)img * 128 + c * KC) * NPIX + p0;
#pragma unroll
        for (int i = 0; i < 4; i++) {
            int idx = tid + i * 256;
            int plane = idx >> 9, rem = idx & 511;
            int row = rem >> 4, seg = rem & 15;
            const u16* src = (plane ? Bl_g : Bh_g) + bbase + (size_t)row * NPIX + seg * 8;
            cpasync16(sm0 + R_OFF_B0 + s * BB_STAGE + plane * BB_PLANE
                      + row * BB_PITCH + seg * 16, src);
        }
    };

    const int lr  = lane & 7;
    const int lth = (lane >> 3) & 1;
    const int ltv = lane >> 4;
    const u32 a_row = (u32)(wm * 64 + lth * 8 + lr);

    copyB(0, 0); cp_commit();

#pragma unroll 1
    for (int c = 0; c < NCH; c++) {
        const int s = c & 1;
        asm volatile("cp.async.wait_group 0;" ::: "memory");  // B(c) (+A on c=0) landed
        __syncthreads();   // MMA(c-1) reads of stage s^1 done; stage s visible

        if (c + 1 < NCH) { copyB(c + 1, s ^ 1); cp_commit(); }  // overlaps MMA(c)

        const u32 ah = sm0;
        const u32 al = sm0 + AR_PLANE;
        const u32 bh = sm0 + R_OFF_B0 + s * BB_STAGE;
        const u32 bl = bh + BB_PLANE;

#pragma unroll
        for (int kk = 0; kk < KC / 16; kk++) {
            u32 af[4][4];
            u32 bfh[4][2], bfl[4][2];
            const u32 a_off = a_row * AR_PITCH + (c * KC + kk * 16) * 2 + ltv * 16;
            const u32 b_off = (u32)(kk * 16 + lth * 8 + lr) * BB_PITCH + wn * 64 + ltv * 16;
#pragma unroll
            for (int mf = 0; mf < 4; mf++)
                ldm_x4(af[mf], ah + a_off + mf * 16 * AR_PITCH);
#pragma unroll
            for (int nh = 0; nh < 2; nh++) {
                u32 r[4];
                ldm_x4t(r, bh + b_off + nh * 32);
                bfh[nh * 2][0] = r[0]; bfh[nh * 2][1] = r[1];
                bfh[nh * 2 + 1][0] = r[2]; bfh[nh * 2 + 1][1] = r[3];
            }
#pragma unroll
            for (int mf = 0; mf < 4; mf++)
#pragma unroll
                for (int nf = 0; nf < 4; nf++)
                    mma_bf16(acc[mf][nf], af[mf], bfh[nf]);
#pragma unroll
            for (int nh = 0; nh < 2; nh++) {
                u32 r[4];
                ldm_x4t(r, bl + b_off + nh * 32);
                bfl[nh * 2][0] = r[0]; bfl[nh * 2][1] = r[1];
                bfl[nh * 2 + 1][0] = r[2]; bfl[nh * 2 + 1][1] = r[3];
            }
#pragma unroll
            for (int mf = 0; mf < 4; mf++)
#pragma unroll
                for (int nf = 0; nf < 4; nf++)
                    mma_bf16(acc[mf][nf], af[mf], bfl[nf]);
#pragma unroll
            for (int mf = 0; mf < 4; mf++)
                ldm_x4(af[mf], al + a_off + mf * 16 * AR_PITCH);
#pragma unroll
            for (int mf = 0; mf < 4; mf++)
#pragma unroll
                for (int nf = 0; nf < 4; nf++)
                    mma_bf16(acc[mf][nf], af[mf], bfh[nf]);
        }
    }

    const int g = lane >> 2, tg = lane & 3;
#pragma unroll
    for (int mf = 0; mf < 4; mf++) {
#pragma unroll
        for (int half = 0; half < 2; half++) {
            const int m = m0 + wm * 64 + mf * 16 + half * 8 + g;
            const float bias = Bias ? Bias[m] : 0.f;
            const size_t rowb = ((size_t)img * MTOT + m) * NPIX;
            const float* resrow = (EPI == 2) ? &Res[((size_t)img * CDIM + m) * NPIX] : nullptr;
#pragma unroll
            for (int nf = 0; nf < 4; nf++) {
                const int px = p0 + wn * 32 + nf * 8 + 2 * tg;
                float v0 = acc[mf][nf][half * 2 + 0] + bias;
                float v1 = acc[mf][nf][half * 2 + 1] + bias;
                if (EPI == 2) { v0 += resrow[px]; v1 += resrow[px + 1]; }
                if (OUTPL) {
                    u32 hi, lo;
                    split_pack(v0, v1, hi, lo);
                    const size_t hw = (rowb + px) >> 1;
                    reinterpret_cast<u32*>(OutH)[hw] = hi;
                    reinterpret_cast<u32*>(OutL)[hw] = lo;
                } else {
                    *reinterpret_cast<float2*>(&OutF[rowb + px]) = make_float2(v0, v1);
                }
            }
        }
    }
}

// ---------------- fused weight prep ----------------
__global__ void prep_w_all(
    const float* __restrict__ w1, const float* __restrict__ w2,
    const float* __restrict__ wg, const float* __restrict__ wgb,
    const float* __restrict__ wup,
    u16* __restrict__ w1h, u16* __restrict__ w1l,
    u16* __restrict__ w2h, u16* __restrict__ w2l,
    u16* __restrict__ wgh, u16* __restrict__ wgl,
    u16* __restrict__ wgbh, u16* __restrict__ wgbl,
    u16* __restrict__ wuph, u16* __restrict__ wupl)
{
    int i = blockIdx.x * 256 + threadIdx.x;
    const float* src; u16 *dh, *dl; int off;
    if      (i < 32768)  { src = w1;  dh = w1h;  dl = w1l;  off = i; }
    else if (i < 49152)  { src = w2;  dh = w2h;  dl = w2l;  off = i - 32768; }
    else if (i < 81920)  { src = wg;  dh = wgh;  dl = wgl;  off = i - 49152; }
    else if (i < 114688) { src = wgb; dh = wgbh; dl = wgbl; off = i - 81920; }
    else                 { src = wup; dh = wuph; dl = wupl; off = i - 114688; }
    float v = src[off];
    float hf = __bfloat162float(__float2bfloat16(v));
    dh[off] = (u16)(__float_as_uint(hf) >> 16);
    dl[off] = (u16)(__float_as_uint(__bfloat162float(__float2bfloat16(v - hf))) >> 16);
}

// ---------------- depthwise 3x3 + bias + GELU: fp32 in, planes out ----------------
__global__ __launch_bounds__(256) void dw3x3_pl(
    const float* __restrict__ in, const float* __restrict__ wd,
    const float* __restrict__ bd, u16* __restrict__ outH, u16* __restrict__ outL)
{
    int c = blockIdx.y, img = blockIdx.z;
    int pix0 = (blockIdx.x * 256 + threadIdx.x) * 2;
    int h = pix0 >> 7, w0 = pix0 & 127;
    const size_t base = ((size_t)img * CDIM + c) * NPIX;
    const float* p = in + base;
    float wreg[9];
#pragma unroll
    for (int i = 0; i < 9; i++) wreg[i] = wd[c * 9 + i];
    float s0 = bd[c], s1 = bd[c];
#pragma unroll
    for (int ky = 0; ky < 3; ky++) {
        int hh = h + ky - 1;
        if ((unsigned)hh >= 128u) continue;
        float v0 = (w0 - 1 >= 0)   ? p[hh * WW + w0 - 1] : 0.f;
        float v1 = p[hh * WW + w0];
        float v2 = p[hh * WW + w0 + 1];
        float v3 = (w0 + 2 < 128)  ? p[hh * WW + w0 + 2] : 0.f;
        s0 = fmaf(wreg[ky * 3 + 0], v0, s0);
        s0 = fmaf(wreg[ky * 3 + 1], v1, s0);
        s0 = fmaf(wreg[ky * 3 + 2], v2, s0);
        s1 = fmaf(wreg[ky * 3 + 0], v1, s1);
        s1 = fmaf(wreg[ky * 3 + 1], v2, s1);
        s1 = fmaf(wreg[ky * 3 + 2], v3, s1);
    }
    u32 hi, lo;
    split_pack(gelu_exact(s0), gelu_exact(s1), hi, lo);
    reinterpret_cast<u32*>(outH)[(base + pix0) >> 1] = hi;
    reinterpret_cast<u32*>(outL)[(base + pix0) >> 1] = lo;
}

// ---------------- minGRU scan (fp32 in); OUTPL: planes out else fp32 ----------------
template <bool OUTPL>
__global__ __launch_bounds__(256) void gru_scan4(
    const float* __restrict__ hg, float* __restrict__ gF,
    u16* __restrict__ gH, u16* __restrict__ gL)
{
    int c = blockIdx.y, b = blockIdx.z;
    int pix0 = (blockIdx.x * 256 + threadIdx.x) * 4;
    float4 h = make_float4(0.f, 0.f, 0.f, 0.f);
#pragma unroll
    for (int v = 0; v < NV; v++) {
        size_t base = (((size_t)(b * NV + v)) * 2 * CDIM + c) * NPIX + pix0;
        float4 hid = *reinterpret_cast<const float4*>(&hg[base]);
        float4 gt  = *reinterpret_cast<const float4*>(&hg[base + (size_t)CDIM * NPIX]);
        float z, ht;
        z = 1.f / (1.f + expf(-gt.x)); ht = (hid.x >= 0.f) ? (hid.x + 0.5f) : (1.f / (1.f + expf(-hid.x)));
        h.x = (1.f - z) * h.x + z * ht;
        z = 1.f / (1.f + expf(-gt.y)); ht = (hid.y >= 0.f) ? (hid.y + 0.5f) : (1.f / (1.f + expf(-hid.y)));
        h.y = (1.f - z) * h.y + z * ht;
        z = 1.f / (1.f + expf(-gt.z)); ht = (hid.z >= 0.f) ? (hid.z + 0.5f) : (1.f / (1.f + expf(-hid.z)));
        h.z = (1.f - z) * h.z + z * ht;
        z = 1.f / (1.f + expf(-gt.w)); ht = (hid.w >= 0.f) ? (hid.w + 0.5f) : (1.f / (1.f + expf(-hid.w)));
        h.w = (1.f - z) * h.w + z * ht;
        size_t d = (((size_t)(b * NV + v)) * CDIM + c) * NPIX + pix0;
        if (OUTPL) {
            u32 h0, l0, h1, l1;
            split_pack(h.x, h.y, h0, l0);
            split_pack(h.z, h.w, h1, l1);
            *reinterpret_cast<uint2*>(&gH[d]) = make_uint2(h0, h1);
            *reinterpret_cast<uint2*>(&gL[d]) = make_uint2(l0, l1);
        } else {
            *reinterpret_cast<float4*>(&gF[d]) = h;
        }
    }
}

// ---------------- alpha: 3x3 conv C->1 (fp32 in), 2 px/thread with tap reuse ---------
__global__ __launch_bounds__(256) void alpha_conv2(
    const float* __restrict__ g2, const float* __restrict__ aw,
    const float* __restrict__ ab, float* __restrict__ alpha)
{
    __shared__ float w[1152];
    for (int i = threadIdx.x; i < 1152; i += 256) w[i] = aw[i];
    __syncthreads();
    int img = blockIdx.z;
    int pix0 = (blockIdx.x * 256 + threadIdx.x) * 2;
    int h = pix0 >> 7, x0 = pix0 & 127;
    float s0 = ab[0], s1 = ab[0];
    const float* base = g2 + (size_t)img * CDIM * NPIX;
    for (int c = 0; c < CDIM; c++) {
        const float* p  = base + (size_t)c * NPIX;
        const float* wc = w + c * 9;
#pragma unroll
        for (int ky = 0; ky < 3; ky++) {
            int hh = h + ky - 1;
            if ((unsigned)hh >= 128u) continue;
            float v0 = (x0 - 1 >= 0)  ? p[hh * WW + x0 - 1] : 0.f;
            float v1 = p[hh * WW + x0];
            float v2 = p[hh * WW + x0 + 1];
            float v3 = (x0 + 2 < 128) ? p[hh * WW + x0 + 2] : 0.f;
            s0 = fmaf(wc[ky * 3 + 0], v0, s0);
            s0 = fmaf(wc[ky * 3 + 1], v1, s0);
            s0 = fmaf(wc[ky * 3 + 2], v2, s0);
            s1 = fmaf(wc[ky * 3 + 0], v1, s1);
            s1 = fmaf(wc[ky * 3 + 1], v2, s1);
            s1 = fmaf(wc[ky * 3 + 2], v3, s1);
        }
    }
    *reinterpret_cast<float2*>(&alpha[(size_t)img * NPIX + pix0]) = make_float2(s0, s1);
}

// ---------------- softmax pool (fp32 in, planes out) ----------------
__global__ __launch_bounds__(256) void pool_k4pl(
    const float* __restrict__ g2, const float* __restrict__ alpha,
    u16* __restrict__ outH, u16* __restrict__ outL)
{
    int b = blockIdx.z;
    int pix0 = (blockIdx.x * 256 + threadIdx.x) * 4;
    float4 a[NV];
    float4 mx = make_float4(-1e30f, -1e30f, -1e30f, -1e30f);
#pragma unroll
    for (int v = 0; v < NV; v++) {
        a[v] = *reinterpret_cast<const float4*>(&alpha[(size_t)(b * NV + v) * NPIX + pix0]);
        mx.x = fmaxf(mx.x, a[v].x); mx.y = fmaxf(mx.y, a[v].y);
        mx.z = fmaxf(mx.z, a[v].z); mx.w = fmaxf(mx.w, a[v].w);
    }
    float4 sum = make_float4(0.f, 0.f, 0.f, 0.f);
#pragma unroll
    for (int v = 0; v < NV; v++) {
        a[v].x = expf(a[v].x - mx.x); sum.x += a[v].x;
        a[v].y = expf(a[v].y - mx.y); sum.y += a[v].y;
        a[v].z = expf(a[v].z - mx.z); sum.z += a[v].z;
        a[v].w = expf(a[v].w - mx.w); sum.w += a[v].w;
    }
    float4 inv = make_float4(1.f / sum.x, 1.f / sum.y, 1.f / sum.z, 1.f / sum.w);
#pragma unroll
    for (int v = 0; v < NV; v++) {
        a[v].x *= inv.x; a[v].y *= inv.y; a[v].z *= inv.z; a[v].w *= inv.w;
    }
    for (int c = 0; c < CDIM; c++) {
        float4 s = make_float4(0.f, 0.f, 0.f, 0.f);
#pragma unroll
        for (int v = 0; v < NV; v++) {
            float4 gv = *reinterpret_cast<const float4*>(
                &g2[(((size_t)(b * NV + v)) * CDIM + c) * NPIX + pix0]);
            s.x = fmaf(a[v].x, gv.x, s.x);
            s.y = fmaf(a[v].y, gv.y, s.y);
            s.z = fmaf(a[v].z, gv.z, s.z);
            s.w = fmaf(a[v].w, gv.w, s.w);
        }
        size_t d = ((size_t)b * CDIM + c) * NPIX + pix0;
        u32 h0, l0, h1, l1;
        split_pack(s.x, s.y, h0, l0);
        split_pack(s.z, s.w, h1, l1);
        *reinterpret_cast<uint2*>(&outH[d]) = make_uint2(h0, h1);
        *reinterpret_cast<uint2*>(&outL[d]) = make_uint2(l0, l1);
    }
}

// ---------------- pixel-shuffle(4) + 3x3 conv 8->3 (512->512 resize = identity) --------
__global__ __launch_bounds__(256) void outc_k(
    const float* __restrict__ u, const float* __restrict__ wt,
    const float* __restrict__ bs, float* __restrict__ out)
{
    __shared__ float w[216];
    if (threadIdx.x < 216) w[threadIdx.x] = wt[threadIdx.x];
    __syncthreads();
    int b = blockIdx.z, co = blockIdx.y;
    int idx = blockIdx.x * 256 + threadIdx.x;
    int y = idx >> 9, x = idx & 511;
    float s = bs[co];
    const float* ub = u + (size_t)b * CDIM * NPIX;
#pragma unroll
    for (int ky = 0; ky < 3; ky++) {
        int yy = y + ky - 1;
        if ((unsigned)yy >= 512u) continue;
        int sy = yy & 3, hy = yy >> 2;
#pragma unroll
        for (int kx = 0; kx < 3; kx++) {
            int xx = x + kx - 1;
            if ((unsigned)xx >= 512u) continue;
            int sx = xx & 3, hx = xx >> 2;
            const float* up = ub + (size_t)(sy * 4 + sx) * NPIX + hy * WW + hx;
#pragma unroll
            for (int ci = 0; ci < 8; ci++)
                s = fmaf(w[(co * 8 + ci) * 9 + ky * 3 + kx], up[(size_t)ci * 16 * NPIX], s);
        }
    }
    out[((size_t)b * 3 + co) * (512 * 512) + idx] = s;
}

// ---------------- launch ----------------
extern "C" void kernel_launch(void* const* d_in, const int* in_sizes, int n_in,
                              void* d_out, int out_size)
{
    const float* feats     = (const float*)d_in[0];
    const float* prj       = (const float*)d_in[1];
    const float* merge_w1  = (const float*)d_in[2];
    const float* merge_b1  = (const float*)d_in[3];
    const float* merge_wd  = (const float*)d_in[4];
    const float* merge_bd  = (const float*)d_in[5];
    const float* merge_w2  = (const float*)d_in[6];
    const float* merge_b2  = (const float*)d_in[7];
    const float* gru_w     = (const float*)d_in[8];
    const float* gru_bw    = (const float*)d_in[9];
    const float* alpha_w   = (const float*)d_in[10];
    const float* alpha_b   = (const float*)d_in[11];
    const float* up_w      = (const float*)d_in[12];
    const float* up_b      = (const float*)d_in[13];
    const float* outc_w    = (const float*)d_in[14];
    const float* outc_b    = (const float*)d_in[15];

    float *bufA, *bufB, *hg, *alp, *u;
    u16 *dwh, *dwl, *m2h, *m2l, *g1h, *g1l, *plh, *pll;
    u16 *wm1h, *wm1l, *wm2h, *wm2l, *wgh, *wgl, *wgbh, *wgbl, *wuph, *wupl;
    cudaGetSymbolAddress((void**)&bufA, g_bufA);
    cudaGetSymbolAddress((void**)&bufB, g_bufB);
    cudaGetSymbolAddress((void**)&hg,   g_hg);
    cudaGetSymbolAddress((void**)&alp,  g_alp);
    cudaGetSymbolAddress((void**)&u,    g_u);
    cudaGetSymbolAddress((void**)&dwh,  g_dwh);  cudaGetSymbolAddress((void**)&dwl,  g_dwl);
    cudaGetSymbolAddress((void**)&m2h,  g_m2h);  cudaGetSymbolAddress((void**)&m2l,  g_m2l);
    cudaGetSymbolAddress((void**)&g1h,  g_g1h);  cudaGetSymbolAddress((void**)&g1l,  g_g1l);
    cudaGetSymbolAddress((void**)&plh,  g_plh);  cudaGetSymbolAddress((void**)&pll,  g_pll);
    cudaGetSymbolAddress((void**)&wm1h, g_wm1h); cudaGetSymbolAddress((void**)&wm1l, g_wm1l);
    cudaGetSymbolAddress((void**)&wm2h, g_wm2h); cudaGetSymbolAddress((void**)&wm2l, g_wm2l);
    cudaGetSymbolAddress((void**)&wgh,  g_wgh);  cudaGetSymbolAddress((void**)&wgl,  g_wgl);
    cudaGetSymbolAddress((void**)&wgbh, g_wgbh); cudaGetSymbolAddress((void**)&wgbl, g_wgbl);
    cudaGetSymbolAddress((void**)&wuph, g_wuph); cudaGetSymbolAddress((void**)&wupl, g_wupl);

    cudaFuncSetAttribute(gemm_mma<256, 128, 1, true >, cudaFuncAttributeMaxDynamicSharedMemorySize, GSMEM);
    cudaFuncSetAttribute(gemm_pl<128, 2, true >,  cudaFuncAttributeMaxDynamicSharedMemorySize, GSMEM_R);
    cudaFuncSetAttribute(gemm_pl<256, 0, false>,  cudaFuncAttributeMaxDynamicSharedMemorySize, GSMEM_R);
    cudaFuncSetAttribute(gemm_pl<128, 0, false>,  cudaFuncAttributeMaxDynamicSharedMemorySize, GSMEM_R);

    prep_w_all<<<512, 256>>>(merge_w1, merge_w2, gru_w, gru_bw, up_w,
                             wm1h, wm1l, wm2h, wm2l, wgh, wgl, wgbh, wgbl, wuph, wupl);

    // merge1: 1x1 (2C->C) + GELU (fp32 out)
    gemm_mma<256, 128, 1, true ><<<dim3(128, 1, BVI), 256, GSMEM>>>(
        feats, prj, wm1h, wm1l, merge_b1, nullptr, bufA);
    // depthwise 3x3 + GELU -> planes
    dw3x3_pl<<<dim3(32, CDIM, BVI), 256>>>(bufA, merge_wd, merge_bd, dwh, dwl);
    // merge2: planes in, bias + residual(feats), planes out
    gemm_pl<128, 2, true ><<<dim3(128, 1, BVI), 256, GSMEM_R>>>(
        dwh, dwl, wm2h, wm2l, merge_b2, feats, m2h, m2l, nullptr);
    // fwd GRU linear: planes in, fp32 hg out
    gemm_pl<256, 0, false><<<dim3(128, 2, BVI), 256, GSMEM_R>>>(
        m2h, m2l, wgh, wgl, nullptr, nullptr, nullptr, nullptr, hg);
    gru_scan4<true ><<<dim3(16, CDIM, NB), 256>>>(hg, nullptr, g1h, g1l);
    // bwd GRU linear (H-flips cancel -> forward scan): planes in, fp32 hg out
    gemm_pl<256, 0, false><<<dim3(128, 2, BVI), 256, GSMEM_R>>>(
        g1h, g1l, wgbh, wgbl, nullptr, nullptr, nullptr, nullptr, hg);
    gru_scan4<false><<<dim3(16, CDIM, NB), 256>>>(hg, bufB, nullptr, nullptr);
    // alpha conv + softmax pool (fp32 in, planes out)
    alpha_conv2<<<dim3(32, 1, BVI), 256>>>(bufB, alpha_w, alpha_b, alp);
    pool_k4pl<<<dim3(16, 1, NB), 256>>>(bufB, alp, plh, pll);
    // up: planes in, fp32 out
    gemm_pl<128, 0, false><<<dim3(128, 1, NB), 256, GSMEM_R>>>(
        plh, pll, wuph, wupl, up_b, nullptr, nullptr, nullptr, u);
    // pixel shuffle + outc 3x3
    outc_k<<<dim3(1024, 3, NB), 256>>>(u, outc_w, outc_b, (float*)d_out);
}